// round 16
// baseline (speedup 1.0000x reference)
#include <cuda_runtime.h>
#include <cuda_bf16.h>
#include <cstdint>
#include <math.h>

// Problem constants
#define B_      8
#define D_IN_   1024
#define T_      2048
#define CB_SIZE 8192
#define CB_DIM  8
#define NROWS   (B_ * T_)          // 16384
#define EPSV    1e-12f

// Output layout (f32, concatenated in reference return order)
#define OFF_OUT   ((size_t)0)
#define N_OUT     ((size_t)B_ * D_IN_ * T_)             // 16777216
#define OFF_IDX   (N_OUT)                                // 16777216
#define N_IDX     ((size_t)NROWS)                        // 16384
#define OFF_DIST  (OFF_IDX + N_IDX)                      // 16793600
#define N_DIST    ((size_t)NROWS * CB_SIZE)              // 134217728
#define OFF_SCAL  (OFF_DIST + N_DIST)                    // 151011328

// __device__ scratch (no allocations allowed)
__device__ float g_w_in[CB_DIM * D_IN_];     // [c][d]
__device__ float g_w_inT[D_IN_ * CB_DIM];    // [d][c] (for fast k3 staging)
__device__ float g_w_out[D_IN_ * CB_DIM];    // [d][c]
__device__ float g_cbT[CB_DIM * CB_SIZE];    // [k][j], normalized codebook (transposed)
__device__ float g_cnorm[CB_SIZE];           // sum(cb_n^2) per code
__device__ float g_ze[B_ * CB_DIM * T_];     // [b][c][t]
__device__ float g_counts[CB_SIZE];
__device__ int   g_idx[NROWS];
__device__ float g_loss;

// cp.async helpers
#define CP_ASYNC16(smem_u32, gptr) \
    asm volatile("cp.async.cg.shared.global [%0], [%1], 16;" :: "r"(smem_u32), "l"(gptr))
#define CP_COMMIT() asm volatile("cp.async.commit_group;")
#define CP_WAIT1()  asm volatile("cp.async.wait_group 1;")
#define CP_WAIT0()  asm volatile("cp.async.wait_group 0;")

// packed f32x2 helpers (each half = IEEE RN, bit-identical to scalar)
typedef unsigned long long u64;
__device__ __forceinline__ u64 pack2(float x, float y) {
    u64 r; asm("mov.b64 %0, {%1,%2};" : "=l"(r) : "f"(x), "f"(y)); return r;
}
__device__ __forceinline__ void unpack2(u64 v, float& x, float& y) {
    asm("mov.b64 {%0,%1}, %2;" : "=f"(x), "=f"(y) : "l"(v));
}
__device__ __forceinline__ u64 fma2(u64 a, u64 b, u64 c) {
    u64 d; asm("fma.rn.f32x2 %0, %1, %2, %3;" : "=l"(d) : "l"(a), "l"(b), "l"(c)); return d;
}

// XLA:CPU / NEON 4-lane vectorized-reduce pattern for 8-element sum of squares:
//   lane acc: a_l = x_l^2 + x_{l+4}^2, horizontal (a0+a2) + (a1+a3)
__device__ __forceinline__ float sum8_sq_xla(const float x[8])
{
    float a0 = __fadd_rn(__fmul_rn(x[0], x[0]), __fmul_rn(x[4], x[4]));
    float a1 = __fadd_rn(__fmul_rn(x[1], x[1]), __fmul_rn(x[5], x[5]));
    float a2 = __fadd_rn(__fmul_rn(x[2], x[2]), __fmul_rn(x[6], x[6]));
    float a3 = __fadd_rn(__fmul_rn(x[3], x[3]), __fmul_rn(x[7], x[7]));
    return __fadd_rn(__fadd_rn(a0, a2), __fadd_rn(a1, a3));
}

// ---------------------------------------------------------------------------
// K12 (merged prep): block 0 = weight norms (+loss zero), blocks 1..32 =
// codebook normalize + counts zero. 33 blocks x 256. Frozen arithmetic.
// ---------------------------------------------------------------------------
__global__ void k12_prep(const float* __restrict__ v_in, const float* __restrict__ g_in,
                         const float* __restrict__ v_out, const float* __restrict__ g_out,
                         const float* __restrict__ codebook)
{
    int tid = threadIdx.x;

    if (blockIdx.x == 0) {
        __shared__ float s_a[CB_DIM][4];
        __shared__ float s_norm[CB_DIM];

        if (tid < 32) {
            int row = tid >> 2, l = tid & 3;
            const float* v = v_in + row * D_IN_;
            float a = 0.f;
            #pragma unroll 8
            for (int i = 0; i < D_IN_ / 4; i++) {
                float x = v[4 * i + l];
                a = __fadd_rn(a, __fmul_rn(x, x));
            }
            s_a[row][l] = a;
        }
        __syncthreads();
        if (tid < CB_DIM) {
            float h = __fadd_rn(__fadd_rn(s_a[tid][0], s_a[tid][2]),
                                __fadd_rn(s_a[tid][1], s_a[tid][3]));
            s_norm[tid] = fmaxf(__fsqrt_rn(h), EPSV);
        }
        __syncthreads();

        for (int i = tid; i < CB_DIM * D_IN_; i += 256) {
            int c = i >> 10, d = i & 1023;
            float w = __fdiv_rn(__fmul_rn(g_in[c], v_in[i]), s_norm[c]);
            g_w_in[i] = w;
            g_w_inT[d * CB_DIM + c] = w;
        }
        for (int d = tid; d < D_IN_; d += 256) {
            float v[CB_DIM];
            #pragma unroll
            for (int c = 0; c < CB_DIM; c++) v[c] = v_out[d * CB_DIM + c];
            float nrm = fmaxf(__fsqrt_rn(sum8_sq_xla(v)), EPSV);
            float g = g_out[d];
            #pragma unroll
            for (int c = 0; c < CB_DIM; c++)
                g_w_out[d * CB_DIM + c] = __fdiv_rn(__fmul_rn(g, v[c]), nrm);
        }
        if (tid == 0) g_loss = 0.f;
    } else {
        int j = (blockIdx.x - 1) * 256 + tid;
        float v[CB_DIM];
        #pragma unroll
        for (int c = 0; c < CB_DIM; c++) v[c] = codebook[(size_t)j * CB_DIM + c];
        float nrm = fmaxf(__fsqrt_rn(sum8_sq_xla(v)), EPSV);
        float x[CB_DIM];
        #pragma unroll
        for (int c = 0; c < CB_DIM; c++) {
            x[c] = __fdiv_rn(v[c], nrm);
            g_cbT[c * CB_SIZE + j] = x[c];
        }
        g_cnorm[j] = sum8_sq_xla(x);
        g_counts[j] = 0.f;
    }
}

// ---------------------------------------------------------------------------
// K3: z_e — strict sequential fma over d (frozen order). Chunked cp.async
// double-buffering + packed f32x2 accumulators (each half rounds exactly
// like the scalar chain -> bit-identical). 512 blocks x 32 threads.
// ---------------------------------------------------------------------------
#define K3_CD 32                     // d's per chunk
#define K3_NC (D_IN_ / K3_CD)        // 32 chunks

__global__ void __launch_bounds__(32)
k3_ze(const float* __restrict__ z, const float* __restrict__ b_in)
{
    __shared__ float s_w[2][K3_CD * CB_DIM];   // [d][c], 1 KB each
    __shared__ float s_z[2][K3_CD * 32];       // [d][t], 4 KB each

    int tid = threadIdx.x;
    int row0 = blockIdx.x * 32;                // 32 consecutive rows, same b
    int b = row0 >> 11, t0 = row0 & (T_ - 1);
    const float* zbase = z + (size_t)b * D_IN_ * T_ + t0;

    unsigned sz0 = (unsigned)__cvta_generic_to_shared(&s_z[0][0]);
    unsigned sz1 = (unsigned)__cvta_generic_to_shared(&s_z[1][0]);
    unsigned sw0 = (unsigned)__cvta_generic_to_shared(&s_w[0][0]);
    unsigned sw1 = (unsigned)__cvta_generic_to_shared(&s_w[1][0]);

    #define K3_LOAD_CHUNK(szb, swb, ch)                                       \
        _Pragma("unroll")                                                     \
        for (int l = 0; l < 8; l++) {                                         \
            int idx = l * 32 + tid;                                           \
            int d = idx >> 3, t4 = idx & 7;                                   \
            CP_ASYNC16(szb + (unsigned)(d * 128 + t4 * 16),                   \
                       zbase + (size_t)((ch) * K3_CD + d) * T_ + t4 * 4);     \
        }                                                                     \
        _Pragma("unroll")                                                     \
        for (int l = 0; l < 2; l++) {                                         \
            int idx = l * 32 + tid;                                           \
            CP_ASYNC16(swb + (unsigned)(idx * 16),                            \
                       g_w_inT + (ch) * (K3_CD * CB_DIM) + idx * 4);          \
        }

    u64 acc01 = 0ull, acc23 = 0ull, acc45 = 0ull, acc67 = 0ull;

    // prologue: chunk 0 in flight
    K3_LOAD_CHUNK(sz0, sw0, 0)
    CP_COMMIT();

    int cur = 0;
    for (int j = 0; j < K3_NC; j++) {
        if (j + 1 < K3_NC) {
            if (cur == 0) { K3_LOAD_CHUNK(sz1, sw1, j + 1) }
            else          { K3_LOAD_CHUNK(sz0, sw0, j + 1) }
            CP_COMMIT();
            CP_WAIT1();
        } else {
            CP_WAIT0();
        }
        __syncwarp();

        // compute chunk j: ascending d (frozen order); f32x2 pairs
        const float* zs = s_z[cur];
        const u64*   ws = (const u64*)s_w[cur];
        #pragma unroll
        for (int dd = 0; dd < K3_CD; dd++) {
            float vu = zs[dd * 32 + tid];
            u64 vup = pack2(vu, vu);
            acc01 = fma2(ws[dd * 4 + 0], vup, acc01);
            acc23 = fma2(ws[dd * 4 + 1], vup, acc23);
            acc45 = fma2(ws[dd * 4 + 2], vup, acc45);
            acc67 = fma2(ws[dd * 4 + 3], vup, acc67);
        }
        __syncwarp();   // all lanes done with buffer 'cur' before refill
        cur ^= 1;
    }
    #undef K3_LOAD_CHUNK

    float acc[CB_DIM];
    unpack2(acc01, acc[0], acc[1]);
    unpack2(acc23, acc[2], acc[3]);
    unpack2(acc45, acc[4], acc[5]);
    unpack2(acc67, acc[6], acc[7]);

    int t = t0 + tid;
    #pragma unroll
    for (int c = 0; c < CB_DIM; c++)
        g_ze[((size_t)b * CB_DIM + c) * T_ + t] = __fadd_rn(acc[c], b_in[c]);
}

// ---------------------------------------------------------------------------
// K4: dist (streamed store) + argmin + fused counts/loss.
// EXACT R5 configuration (measured 119.9us): 1024 blocks x 128 threads,
// 16 rows/block, 4 rows/warp, 4 cols/lane. Arithmetic frozen.
// ---------------------------------------------------------------------------
#define K4_ROWS 16
#define K4_CHUNK 1024

__global__ void __launch_bounds__(128)
k4_dist(const float* __restrict__ codebook,
        float* __restrict__ dist_out, float* __restrict__ idxf_out)
{
    __shared__ float s_cbT[CB_DIM][K4_CHUNK];
    __shared__ float s_cn[K4_CHUNK];
    __shared__ float s_raw[K4_ROWS][CB_DIM];
    __shared__ float s_e[K4_ROWS][CB_DIM];
    __shared__ float s_en[K4_ROWS];
    __shared__ int   s_idx[K4_ROWS];

    int tid = threadIdx.x;
    int row0 = blockIdx.x * K4_ROWS;

    {
        int r = tid >> 3, c = tid & 7;
        int row = row0 + r;
        int b = row >> 11, t = row & (T_ - 1);
        s_raw[r][c] = g_ze[((size_t)b * CB_DIM + c) * T_ + t];
    }
    __syncthreads();
    if (tid < K4_ROWS) {
        float v[CB_DIM];
        #pragma unroll
        for (int c = 0; c < CB_DIM; c++) v[c] = s_raw[tid][c];
        float nrm = fmaxf(__fsqrt_rn(sum8_sq_xla(v)), EPSV);
        float x[CB_DIM];
        #pragma unroll
        for (int c = 0; c < CB_DIM; c++) {
            x[c] = __fdiv_rn(v[c], nrm);
            s_e[tid][c] = x[c];
        }
        s_en[tid] = sum8_sq_xla(x);
    }
    __syncthreads();

    int warp = tid >> 5, lane = tid & 31;
    float e[4][CB_DIM], en[4];
    float* dp[4];
    #pragma unroll
    for (int r = 0; r < 4; r++) {
        int rr = warp * 4 + r;
        en[r] = s_en[rr];
        #pragma unroll
        for (int k = 0; k < CB_DIM; k++) e[r][k] = s_e[rr][k];
        dp[r] = dist_out + (size_t)(row0 + rr) * CB_SIZE;
    }

    float minv[4] = {3.4e38f, 3.4e38f, 3.4e38f, 3.4e38f};
    int   mini[4] = {0, 0, 0, 0};

    for (int ch = 0; ch < CB_SIZE / K4_CHUNK; ch++) {
        __syncthreads();
        for (int i = tid; i < CB_DIM * (K4_CHUNK / 4); i += 128) {
            int k = i / (K4_CHUNK / 4);
            int j4 = i % (K4_CHUNK / 4);
            ((float4*)s_cbT[k])[j4] =
                ((const float4*)(g_cbT + k * CB_SIZE + ch * K4_CHUNK))[j4];
        }
        for (int i = tid; i < K4_CHUNK / 4; i += 128)
            ((float4*)s_cn)[i] = ((const float4*)(g_cnorm + ch * K4_CHUNK))[i];
        __syncthreads();

        #pragma unroll
        for (int it = 0; it < K4_CHUNK / 128; it++) {
            int cbase = it * 128 + lane * 4;
            float4 c4[CB_DIM];
            #pragma unroll
            for (int k = 0; k < CB_DIM; k++) c4[k] = *(const float4*)&s_cbT[k][cbase];
            float4 cn4 = *(const float4*)&s_cn[cbase];
            int gcol = ch * K4_CHUNK + cbase;

            #pragma unroll
            for (int r = 0; r < 4; r++) {
                float tx = 0.f, ty = 0.f, tz = 0.f, tw = 0.f;
                #pragma unroll
                for (int k = 0; k < CB_DIM; k++) {
                    tx = __fmaf_rn(e[r][k], c4[k].x, tx);
                    ty = __fmaf_rn(e[r][k], c4[k].y, ty);
                    tz = __fmaf_rn(e[r][k], c4[k].z, tz);
                    tw = __fmaf_rn(e[r][k], c4[k].w, tw);
                }
                float4 d4;
                d4.x = __fadd_rn(__fadd_rn(en[r], -(2.f * tx)), cn4.x);
                d4.y = __fadd_rn(__fadd_rn(en[r], -(2.f * ty)), cn4.y);
                d4.z = __fadd_rn(__fadd_rn(en[r], -(2.f * tz)), cn4.z);
                d4.w = __fadd_rn(__fadd_rn(en[r], -(2.f * tw)), cn4.w);

                __stcs((float4*)(dp[r] + gcol), d4);

                float m = fminf(fminf(d4.x, d4.y), fminf(d4.z, d4.w));
                if (m < minv[r]) {
                    minv[r] = m;
                    int off = (d4.x == m) ? 0 : (d4.y == m) ? 1 : (d4.z == m) ? 2 : 3;
                    mini[r] = gcol + off;
                }
            }
        }
    }

    #pragma unroll
    for (int r = 0; r < 4; r++) {
        float v = minv[r]; int i = mini[r];
        #pragma unroll
        for (int off = 16; off; off >>= 1) {
            float ov = __shfl_down_sync(0xffffffffu, v, off);
            int   oi = __shfl_down_sync(0xffffffffu, i, off);
            if (ov < v || (ov == v && oi < i)) { v = ov; i = oi; }
        }
        if (lane == 0) {
            int rr = warp * 4 + r;
            g_idx[row0 + rr] = i;
            idxf_out[row0 + rr] = (float)i;
            s_idx[rr] = i;
        }
    }
    __syncthreads();

    if (tid < K4_ROWS) {
        int idx = s_idx[tid];
        atomicAdd(&g_counts[idx], 1.f);
        const float* cb = codebook + (size_t)idx * CB_DIM;
        float s = 0.f;
        #pragma unroll
        for (int c = 0; c < CB_DIM; c++) {
            float d = s_raw[tid][c] - cb[c];
            s = fmaf(d, d, s);
        }
        s += __shfl_down_sync(0x0000ffffu, s, 8);
        s += __shfl_down_sync(0x0000ffffu, s, 4);
        s += __shfl_down_sync(0x0000ffffu, s, 2);
        s += __shfl_down_sync(0x0000ffffu, s, 1);
        if (tid == 0) atomicAdd(&g_loss, s);
    }
}

// ---------------------------------------------------------------------------
// K6: out = b_out + w_out @ z_q_st ; float4 over t, 16 d-rows per block.
// grid (4 tch, 8 b, 64 dch) x 128 = 2048 blocks.
// ---------------------------------------------------------------------------
__global__ void __launch_bounds__(128)
k6_out(const float* __restrict__ codebook, const float* __restrict__ b_out,
       float* __restrict__ out)
{
    __shared__ float s_w[16][CB_DIM];
    __shared__ float s_b[16];
    int tid = threadIdx.x;
    int tch = blockIdx.x, b = blockIdx.y, dch = blockIdx.z;

    if (tid < 16 * CB_DIM) {
        int dd = tid >> 3, c = tid & 7;
        s_w[dd][c] = g_w_out[(dch * 16 + dd) * CB_DIM + c];
    }
    if (tid < 16) s_b[tid] = b_out[dch * 16 + tid];
    __syncthreads();

    int t0 = tch * 512 + tid * 4;   // 4 consecutive t per thread
    float q[4][CB_DIM];
    #pragma unroll
    for (int j = 0; j < 4; j++) {
        int idx = g_idx[b * T_ + t0 + j];
        const float* cb = codebook + (size_t)idx * CB_DIM;
        #pragma unroll
        for (int c = 0; c < CB_DIM; c++) {
            float ze = g_ze[((size_t)b * CB_DIM + c) * T_ + t0 + j];
            float zq = cb[c];
            q[j][c] = __fadd_rn(ze, __fadd_rn(zq, -ze));   // straight-through
        }
    }

    float* op = out + ((size_t)b * D_IN_ + dch * 16) * T_ + t0;
    #pragma unroll 4
    for (int dd = 0; dd < 16; dd++) {
        float4 o;
        float bb = s_b[dd];
        const float* w = s_w[dd];
        float a0 = 0.f, a1 = 0.f, a2 = 0.f, a3 = 0.f;
        #pragma unroll
        for (int c = 0; c < CB_DIM; c++) {
            float wc = w[c];
            a0 = __fmaf_rn(wc, q[0][c], a0);
            a1 = __fmaf_rn(wc, q[1][c], a1);
            a2 = __fmaf_rn(wc, q[2][c], a2);
            a3 = __fmaf_rn(wc, q[3][c], a3);
        }
        o.x = __fadd_rn(a0, bb);
        o.y = __fadd_rn(a1, bb);
        o.z = __fadd_rn(a2, bb);
        o.w = __fadd_rn(a3, bb);
        *(float4*)(op + (size_t)dd * T_) = o;
    }
}

// ---------------------------------------------------------------------------
// K7: scalars (vq_loss, perplexity, active_num). 1 block x 256.
// ---------------------------------------------------------------------------
__global__ void k7_final(float* __restrict__ scal)
{
    __shared__ float s_s[256];
    __shared__ float s_a[256];
    int tid = threadIdx.x;
    float s = 0.f, a = 0.f;
    for (int i = tid; i < CB_SIZE; i += 256) {
        float c = g_counts[i];
        float p = c / (float)NROWS;
        s += p * logf(p + 1e-10f);
        if (c * (1.0f - 0.99f) > 2.0f) a += 1.f;
    }
    s_s[tid] = s; s_a[tid] = a;
    __syncthreads();
    for (int off = 128; off; off >>= 1) {
        if (tid < off) { s_s[tid] += s_s[tid + off]; s_a[tid] += s_a[tid + off]; }
        __syncthreads();
    }
    if (tid == 0) {
        scal[0] = g_loss * 1.25f / (float)(B_ * CB_DIM * T_);  // vq_loss
        scal[1] = expf(-s_s[0]);                               // perplexity
        scal[2] = s_a[0];                                      // active_num
    }
}

// ---------------------------------------------------------------------------
extern "C" void kernel_launch(void* const* d_in, const int* in_sizes, int n_in,
                              void* d_out, int out_size)
{
    const float* z        = (const float*)d_in[0];
    const float* codebook = (const float*)d_in[1];
    const float* v_in     = (const float*)d_in[2];
    const float* g_in     = (const float*)d_in[3];
    const float* b_in     = (const float*)d_in[4];
    const float* v_out    = (const float*)d_in[5];
    const float* g_out    = (const float*)d_in[6];
    const float* b_out    = (const float*)d_in[7];
    float* out = (float*)d_out;

    k12_prep<<<33, 256>>>(v_in, g_in, v_out, g_out, codebook);
    k3_ze<<<512, 32>>>(z, b_in);
    k4_dist<<<NROWS / K4_ROWS, 128>>>(codebook, out + OFF_DIST, out + OFF_IDX);
    k6_out<<<dim3(4, 8, 64), 128>>>(codebook, b_out, out + OFF_OUT);
    k7_final<<<1, 256>>>(out + OFF_SCAL);
}

// round 17
// speedup vs baseline: 1.4428x; 1.4428x over previous
#include <cuda_runtime.h>
#include <cuda_bf16.h>
#include <cstdint>
#include <math.h>

// Problem constants
#define B_      8
#define D_IN_   1024
#define T_      2048
#define CB_SIZE 8192
#define CB_DIM  8
#define NROWS   (B_ * T_)          // 16384
#define EPSV    1e-12f

// Output layout (f32, concatenated in reference return order)
#define OFF_OUT   ((size_t)0)
#define N_OUT     ((size_t)B_ * D_IN_ * T_)             // 16777216
#define OFF_IDX   (N_OUT)                                // 16777216
#define N_IDX     ((size_t)NROWS)                        // 16384
#define OFF_DIST  (OFF_IDX + N_IDX)                      // 16793600
#define N_DIST    ((size_t)NROWS * CB_SIZE)              // 134217728
#define OFF_SCAL  (OFF_DIST + N_DIST)                    // 151011328

// __device__ scratch (no allocations allowed)
__device__ float g_w_in[CB_DIM * D_IN_];     // [c][d]
__device__ float g_w_inT[D_IN_ * CB_DIM];    // [d][c] (for fast k3 staging)
__device__ float g_w_out[D_IN_ * CB_DIM];    // [d][c]
__device__ float g_cbT[CB_DIM * CB_SIZE];    // [k][j], normalized codebook (transposed)
__device__ float g_cnorm[CB_SIZE];           // sum(cb_n^2) per code
__device__ float g_ze[B_ * CB_DIM * T_];     // [b][c][t]
__device__ float g_counts[CB_SIZE];
__device__ int   g_idx[NROWS];
__device__ float g_loss;

// cp.async helpers
#define CP_ASYNC16(smem_u32, gptr) \
    asm volatile("cp.async.cg.shared.global [%0], [%1], 16;" :: "r"(smem_u32), "l"(gptr))
#define CP_COMMIT() asm volatile("cp.async.commit_group;")
#define CP_WAIT2()  asm volatile("cp.async.wait_group 2;")
#define CP_WAIT0()  asm volatile("cp.async.wait_group 0;")

// XLA:CPU / NEON 4-lane vectorized-reduce pattern for 8-element sum of squares:
//   lane acc: a_l = x_l^2 + x_{l+4}^2, horizontal (a0+a2) + (a1+a3)
__device__ __forceinline__ float sum8_sq_xla(const float x[8])
{
    float a0 = __fadd_rn(__fmul_rn(x[0], x[0]), __fmul_rn(x[4], x[4]));
    float a1 = __fadd_rn(__fmul_rn(x[1], x[1]), __fmul_rn(x[5], x[5]));
    float a2 = __fadd_rn(__fmul_rn(x[2], x[2]), __fmul_rn(x[6], x[6]));
    float a3 = __fadd_rn(__fmul_rn(x[3], x[3]), __fmul_rn(x[7], x[7]));
    return __fadd_rn(__fadd_rn(a0, a2), __fadd_rn(a1, a3));
}

// ---------------------------------------------------------------------------
// KZ: zero counts + loss. 32 blocks x 256.
// ---------------------------------------------------------------------------
__global__ void kz_zero()
{
    int i = blockIdx.x * 256 + threadIdx.x;
    g_counts[i] = 0.f;
    if (i == 0) g_loss = 0.f;
}

// ---------------------------------------------------------------------------
// K1: weight-norm for in/out projections (frozen arithmetic). 1 block x 256.
// Also writes the [d][c] transpose of w_in for k3.
// ---------------------------------------------------------------------------
__global__ void k1_prep_w(const float* __restrict__ v_in, const float* __restrict__ g_in,
                          const float* __restrict__ v_out, const float* __restrict__ g_out)
{
    __shared__ float s_a[CB_DIM][4];
    __shared__ float s_norm[CB_DIM];
    int tid = threadIdx.x;

    if (tid < 32) {
        int row = tid >> 2, l = tid & 3;
        const float* v = v_in + row * D_IN_;
        float a = 0.f;
        #pragma unroll 8
        for (int i = 0; i < D_IN_ / 4; i++) {
            float x = v[4 * i + l];
            a = __fadd_rn(a, __fmul_rn(x, x));
        }
        s_a[row][l] = a;
    }
    __syncthreads();
    if (tid < CB_DIM) {
        float h = __fadd_rn(__fadd_rn(s_a[tid][0], s_a[tid][2]),
                            __fadd_rn(s_a[tid][1], s_a[tid][3]));
        s_norm[tid] = fmaxf(__fsqrt_rn(h), EPSV);
    }
    __syncthreads();

    for (int i = tid; i < CB_DIM * D_IN_; i += 256) {
        int c = i >> 10, d = i & 1023;
        float w = __fdiv_rn(__fmul_rn(g_in[c], v_in[i]), s_norm[c]);
        g_w_in[i] = w;
        g_w_inT[d * CB_DIM + c] = w;
    }
    for (int d = tid; d < D_IN_; d += 256) {
        float v[CB_DIM];
        #pragma unroll
        for (int c = 0; c < CB_DIM; c++) v[c] = v_out[d * CB_DIM + c];
        float nrm = fmaxf(__fsqrt_rn(sum8_sq_xla(v)), EPSV);
        float g = g_out[d];
        #pragma unroll
        for (int c = 0; c < CB_DIM; c++)
            g_w_out[d * CB_DIM + c] = __fdiv_rn(__fmul_rn(g, v[c]), nrm);
    }
}

// ---------------------------------------------------------------------------
// K2: normalize codebook -> transposed layout. grid 32 x 256.
// ---------------------------------------------------------------------------
__global__ void k2_prep_cb(const float* __restrict__ codebook)
{
    int j = blockIdx.x * 256 + threadIdx.x;
    float v[CB_DIM];
    #pragma unroll
    for (int c = 0; c < CB_DIM; c++) v[c] = codebook[(size_t)j * CB_DIM + c];
    float nrm = fmaxf(__fsqrt_rn(sum8_sq_xla(v)), EPSV);
    float x[CB_DIM];
    #pragma unroll
    for (int c = 0; c < CB_DIM; c++) {
        x[c] = __fdiv_rn(v[c], nrm);
        g_cbT[c * CB_SIZE + j] = x[c];
    }
    g_cnorm[j] = sum8_sq_xla(x);
}

// ---------------------------------------------------------------------------
// K3: z_e — strict sequential fma over d (frozen order). Chunked, TRIPLE-
// buffered cp.async (depth-3 pipeline; ~1400 cycles of latency cover).
// 512 blocks x 32 threads; ascending-d scalar chain is bit-identical.
// ---------------------------------------------------------------------------
#define K3_CD 32                     // d's per chunk
#define K3_NC (D_IN_ / K3_CD)        // 32 chunks

__global__ void __launch_bounds__(32)
k3_ze(const float* __restrict__ z, const float* __restrict__ b_in)
{
    __shared__ float s_w[3][K3_CD * CB_DIM];   // [d][c], 1 KB each
    __shared__ float s_z[3][K3_CD * 32];       // [d][t], 4 KB each

    int tid = threadIdx.x;
    int row0 = blockIdx.x * 32;                // 32 consecutive rows, same b
    int b = row0 >> 11, t0 = row0 & (T_ - 1);
    const float* zbase = z + (size_t)b * D_IN_ * T_ + t0;

    unsigned szb[3], swb[3];
    #pragma unroll
    for (int s = 0; s < 3; s++) {
        szb[s] = (unsigned)__cvta_generic_to_shared(&s_z[s][0]);
        swb[s] = (unsigned)__cvta_generic_to_shared(&s_w[s][0]);
    }

    // z tile: 32d x 32t = 4KB -> 8 x 16B per thread
    // w chunk: 32d x 8c = 1KB -> 2 x 16B per thread
    #define K3_LOAD_CHUNK(slot, ch)                                           \
        _Pragma("unroll")                                                     \
        for (int l = 0; l < 8; l++) {                                         \
            int idx = l * 32 + tid;                                           \
            int d = idx >> 3, t4 = idx & 7;                                   \
            CP_ASYNC16(szb[slot] + (unsigned)(d * 128 + t4 * 16),             \
                       zbase + (size_t)((ch) * K3_CD + d) * T_ + t4 * 4);     \
        }                                                                     \
        _Pragma("unroll")                                                     \
        for (int l = 0; l < 2; l++) {                                         \
            int idx = l * 32 + tid;                                           \
            CP_ASYNC16(swb[slot] + (unsigned)(idx * 16),                      \
                       g_w_inT + (ch) * (K3_CD * CB_DIM) + idx * 4);          \
        }

    float acc[CB_DIM] = {0.f, 0.f, 0.f, 0.f, 0.f, 0.f, 0.f, 0.f};

    // prologue: chunks 0 and 1 in flight (one commit group each)
    K3_LOAD_CHUNK(0, 0)
    CP_COMMIT();
    K3_LOAD_CHUNK(1, 1)
    CP_COMMIT();

    int cur = 0;
    for (int j = 0; j < K3_NC; j++) {
        if (j + 2 < K3_NC) {
            int slot = (cur + 2) % 3;
            K3_LOAD_CHUNK(slot, j + 2)
            CP_COMMIT();
            CP_WAIT2();           // chunk j's group complete (<=2 newer pending)
        } else {
            CP_WAIT0();
        }
        __syncwarp();

        // compute chunk j: ascending d (frozen order)
        const float* zs = s_z[cur];
        const float* ws = s_w[cur];
        #pragma unroll
        for (int dd = 0; dd < K3_CD; dd++) {
            float vu = zs[dd * 32 + tid];
            float4 w0 = *(const float4*)&ws[dd * 8];
            float4 w1 = *(const float4*)&ws[dd * 8 + 4];
            acc[0] = __fmaf_rn(w0.x, vu, acc[0]);
            acc[1] = __fmaf_rn(w0.y, vu, acc[1]);
            acc[2] = __fmaf_rn(w0.z, vu, acc[2]);
            acc[3] = __fmaf_rn(w0.w, vu, acc[3]);
            acc[4] = __fmaf_rn(w1.x, vu, acc[4]);
            acc[5] = __fmaf_rn(w1.y, vu, acc[5]);
            acc[6] = __fmaf_rn(w1.z, vu, acc[6]);
            acc[7] = __fmaf_rn(w1.w, vu, acc[7]);
        }
        __syncwarp();   // all lanes done with buffer 'cur' before refill
        cur = (cur + 1) % 3;
    }
    #undef K3_LOAD_CHUNK

    int t = t0 + tid;
    #pragma unroll
    for (int c = 0; c < CB_DIM; c++)
        g_ze[((size_t)b * CB_DIM + c) * T_ + t] = __fadd_rn(acc[c], b_in[c]);
}

// ---------------------------------------------------------------------------
// K4: dist (streamed store) + argmin + fused counts/loss.
// EXACT R5 configuration (measured 119.9us): 1024 blocks x 128 threads,
// 16 rows/block, 4 rows/warp, 4 cols/lane. Arithmetic frozen.
// ---------------------------------------------------------------------------
#define K4_ROWS 16
#define K4_CHUNK 1024

__global__ void __launch_bounds__(128)
k4_dist(const float* __restrict__ codebook,
        float* __restrict__ dist_out, float* __restrict__ idxf_out)
{
    __shared__ float s_cbT[CB_DIM][K4_CHUNK];
    __shared__ float s_cn[K4_CHUNK];
    __shared__ float s_raw[K4_ROWS][CB_DIM];
    __shared__ float s_e[K4_ROWS][CB_DIM];
    __shared__ float s_en[K4_ROWS];
    __shared__ int   s_idx[K4_ROWS];

    int tid = threadIdx.x;
    int row0 = blockIdx.x * K4_ROWS;

    {
        int r = tid >> 3, c = tid & 7;
        int row = row0 + r;
        int b = row >> 11, t = row & (T_ - 1);
        s_raw[r][c] = g_ze[((size_t)b * CB_DIM + c) * T_ + t];
    }
    __syncthreads();
    if (tid < K4_ROWS) {
        float v[CB_DIM];
        #pragma unroll
        for (int c = 0; c < CB_DIM; c++) v[c] = s_raw[tid][c];
        float nrm = fmaxf(__fsqrt_rn(sum8_sq_xla(v)), EPSV);
        float x[CB_DIM];
        #pragma unroll
        for (int c = 0; c < CB_DIM; c++) {
            x[c] = __fdiv_rn(v[c], nrm);
            s_e[tid][c] = x[c];
        }
        s_en[tid] = sum8_sq_xla(x);
    }
    __syncthreads();

    int warp = tid >> 5, lane = tid & 31;
    float e[4][CB_DIM], en[4];
    float* dp[4];
    #pragma unroll
    for (int r = 0; r < 4; r++) {
        int rr = warp * 4 + r;
        en[r] = s_en[rr];
        #pragma unroll
        for (int k = 0; k < CB_DIM; k++) e[r][k] = s_e[rr][k];
        dp[r] = dist_out + (size_t)(row0 + rr) * CB_SIZE;
    }

    float minv[4] = {3.4e38f, 3.4e38f, 3.4e38f, 3.4e38f};
    int   mini[4] = {0, 0, 0, 0};

    for (int ch = 0; ch < CB_SIZE / K4_CHUNK; ch++) {
        __syncthreads();
        for (int i = tid; i < CB_DIM * (K4_CHUNK / 4); i += 128) {
            int k = i / (K4_CHUNK / 4);
            int j4 = i % (K4_CHUNK / 4);
            ((float4*)s_cbT[k])[j4] =
                ((const float4*)(g_cbT + k * CB_SIZE + ch * K4_CHUNK))[j4];
        }
        for (int i = tid; i < K4_CHUNK / 4; i += 128)
            ((float4*)s_cn)[i] = ((const float4*)(g_cnorm + ch * K4_CHUNK))[i];
        __syncthreads();

        #pragma unroll
        for (int it = 0; it < K4_CHUNK / 128; it++) {
            int cbase = it * 128 + lane * 4;
            float4 c4[CB_DIM];
            #pragma unroll
            for (int k = 0; k < CB_DIM; k++) c4[k] = *(const float4*)&s_cbT[k][cbase];
            float4 cn4 = *(const float4*)&s_cn[cbase];
            int gcol = ch * K4_CHUNK + cbase;

            #pragma unroll
            for (int r = 0; r < 4; r++) {
                float tx = 0.f, ty = 0.f, tz = 0.f, tw = 0.f;
                #pragma unroll
                for (int k = 0; k < CB_DIM; k++) {
                    tx = __fmaf_rn(e[r][k], c4[k].x, tx);
                    ty = __fmaf_rn(e[r][k], c4[k].y, ty);
                    tz = __fmaf_rn(e[r][k], c4[k].z, tz);
                    tw = __fmaf_rn(e[r][k], c4[k].w, tw);
                }
                float4 d4;
                d4.x = __fadd_rn(__fadd_rn(en[r], -(2.f * tx)), cn4.x);
                d4.y = __fadd_rn(__fadd_rn(en[r], -(2.f * ty)), cn4.y);
                d4.z = __fadd_rn(__fadd_rn(en[r], -(2.f * tz)), cn4.z);
                d4.w = __fadd_rn(__fadd_rn(en[r], -(2.f * tw)), cn4.w);

                __stcs((float4*)(dp[r] + gcol), d4);

                float m = fminf(fminf(d4.x, d4.y), fminf(d4.z, d4.w));
                if (m < minv[r]) {
                    minv[r] = m;
                    int off = (d4.x == m) ? 0 : (d4.y == m) ? 1 : (d4.z == m) ? 2 : 3;
                    mini[r] = gcol + off;
                }
            }
        }
    }

    #pragma unroll
    for (int r = 0; r < 4; r++) {
        float v = minv[r]; int i = mini[r];
        #pragma unroll
        for (int off = 16; off; off >>= 1) {
            float ov = __shfl_down_sync(0xffffffffu, v, off);
            int   oi = __shfl_down_sync(0xffffffffu, i, off);
            if (ov < v || (ov == v && oi < i)) { v = ov; i = oi; }
        }
        if (lane == 0) {
            int rr = warp * 4 + r;
            g_idx[row0 + rr] = i;
            idxf_out[row0 + rr] = (float)i;
            s_idx[rr] = i;
        }
    }
    __syncthreads();

    if (tid < K4_ROWS) {
        int idx = s_idx[tid];
        atomicAdd(&g_counts[idx], 1.f);
        const float* cb = codebook + (size_t)idx * CB_DIM;
        float s = 0.f;
        #pragma unroll
        for (int c = 0; c < CB_DIM; c++) {
            float d = s_raw[tid][c] - cb[c];
            s = fmaf(d, d, s);
        }
        s += __shfl_down_sync(0x0000ffffu, s, 8);
        s += __shfl_down_sync(0x0000ffffu, s, 4);
        s += __shfl_down_sync(0x0000ffffu, s, 2);
        s += __shfl_down_sync(0x0000ffffu, s, 1);
        if (tid == 0) atomicAdd(&g_loss, s);
    }
}

// ---------------------------------------------------------------------------
// K6: out = b_out + w_out @ z_q_st ; float4 over t, 32 d-rows per block.
// grid (4 tch, 8 b, 32 dch) x 128 = 1024 blocks. (R15 config, 20us)
// ---------------------------------------------------------------------------
__global__ void __launch_bounds__(128)
k6_out(const float* __restrict__ codebook, const float* __restrict__ b_out,
       float* __restrict__ out)
{
    __shared__ float s_w[32][CB_DIM];
    __shared__ float s_b[32];
    int tid = threadIdx.x;
    int tch = blockIdx.x, b = blockIdx.y, dch = blockIdx.z;

    for (int i = tid; i < 32 * CB_DIM; i += 128) {
        int dd = i >> 3, c = i & 7;
        s_w[dd][c] = g_w_out[(dch * 32 + dd) * CB_DIM + c];
    }
    if (tid < 32) s_b[tid] = b_out[dch * 32 + tid];
    __syncthreads();

    int t0 = tch * 512 + tid * 4;   // 4 consecutive t per thread
    float q[4][CB_DIM];
    #pragma unroll
    for (int j = 0; j < 4; j++) {
        int idx = g_idx[b * T_ + t0 + j];
        const float* cb = codebook + (size_t)idx * CB_DIM;
        #pragma unroll
        for (int c = 0; c < CB_DIM; c++) {
            float ze = g_ze[((size_t)b * CB_DIM + c) * T_ + t0 + j];
            float zq = cb[c];
            q[j][c] = __fadd_rn(ze, __fadd_rn(zq, -ze));   // straight-through
        }
    }

    float* op = out + ((size_t)b * D_IN_ + dch * 32) * T_ + t0;
    #pragma unroll 4
    for (int dd = 0; dd < 32; dd++) {
        float4 o;
        float bb = s_b[dd];
        const float* w = s_w[dd];
        float a0 = 0.f, a1 = 0.f, a2 = 0.f, a3 = 0.f;
        #pragma unroll
        for (int c = 0; c < CB_DIM; c++) {
            float wc = w[c];
            a0 = __fmaf_rn(wc, q[0][c], a0);
            a1 = __fmaf_rn(wc, q[1][c], a1);
            a2 = __fmaf_rn(wc, q[2][c], a2);
            a3 = __fmaf_rn(wc, q[3][c], a3);
        }
        o.x = __fadd_rn(a0, bb);
        o.y = __fadd_rn(a1, bb);
        o.z = __fadd_rn(a2, bb);
        o.w = __fadd_rn(a3, bb);
        *(float4*)(op + (size_t)dd * T_) = o;
    }
}

// ---------------------------------------------------------------------------
// K7: scalars (vq_loss, perplexity, active_num). 1 block x 256.
// ---------------------------------------------------------------------------
__global__ void k7_final(float* __restrict__ scal)
{
    __shared__ float s_s[256];
    __shared__ float s_a[256];
    int tid = threadIdx.x;
    float s = 0.f, a = 0.f;
    for (int i = tid; i < CB_SIZE; i += 256) {
        float c = g_counts[i];
        float p = c / (float)NROWS;
        s += p * logf(p + 1e-10f);
        if (c * (1.0f - 0.99f) > 2.0f) a += 1.f;
    }
    s_s[tid] = s; s_a[tid] = a;
    __syncthreads();
    for (int off = 128; off; off >>= 1) {
        if (tid < off) { s_s[tid] += s_s[tid + off]; s_a[tid] += s_a[tid + off]; }
        __syncthreads();
    }
    if (tid == 0) {
        scal[0] = g_loss * 1.25f / (float)(B_ * CB_DIM * T_);  // vq_loss
        scal[1] = expf(-s_s[0]);                               // perplexity
        scal[2] = s_a[0];                                      // active_num
    }
}

// ---------------------------------------------------------------------------
extern "C" void kernel_launch(void* const* d_in, const int* in_sizes, int n_in,
                              void* d_out, int out_size)
{
    const float* z        = (const float*)d_in[0];
    const float* codebook = (const float*)d_in[1];
    const float* v_in     = (const float*)d_in[2];
    const float* g_in     = (const float*)d_in[3];
    const float* b_in     = (const float*)d_in[4];
    const float* v_out    = (const float*)d_in[5];
    const float* g_out    = (const float*)d_in[6];
    const float* b_out    = (const float*)d_in[7];
    float* out = (float*)d_out;

    // launch order chosen so the 4th launch (ncu capture slot) is k3
    kz_zero<<<32, 256>>>();
    k1_prep_w<<<1, 256>>>(v_in, g_in, v_out, g_out);
    k2_prep_cb<<<32, 256>>>(codebook);
    k3_ze<<<512, 32>>>(z, b_in);
    k4_dist<<<NROWS / K4_ROWS, 128>>>(codebook, out + OFF_DIST, out + OFF_IDX);
    k6_out<<<dim3(4, 8, 32), 128>>>(codebook, b_out, out + OFF_OUT);
    k7_final<<<1, 256>>>(out + OFF_SCAL);
}